// round 3
// baseline (speedup 1.0000x reference)
#include <cuda_runtime.h>

typedef unsigned long long ull;

#define TPB 256
#define BM  64
#define BN  128
#define KK  128
#define SAS 130

static const int MAXN = 50000;

__device__ float g_Q [MAXN * 128];
__device__ float g_K [MAXN * 128];
__device__ float g_V [MAXN * 128];
__device__ float g_wV[MAXN * 128];
__device__ float g_z [MAXN * 8];

// ---------- packed f32x2 helpers ----------
__device__ __forceinline__ ull pk(float lo, float hi) {
    ull r; asm("mov.b64 %0, {%1, %2};" : "=l"(r) : "f"(lo), "f"(hi)); return r;
}
__device__ __forceinline__ void fma2(ull& d, ull a, ull b) {
    asm("fma.rn.f32x2 %0, %1, %2, %0;" : "+l"(d) : "l"(a), "l"(b));
}
__device__ __forceinline__ void upk(ull v, float& lo, float& hi) {
    asm("mov.b64 {%0, %1}, %2;" : "=f"(lo), "=f"(hi) : "l"(v));
}
__device__ __forceinline__ void red_v4(float* p, float a, float b, float c, float d) {
    asm volatile("red.global.add.v4.f32 [%0], {%1, %2, %3, %4};"
                 :: "l"(p), "f"(a), "f"(b), "f"(c), "f"(d) : "memory");
}
__device__ __forceinline__ void red_f32(float* p, float a) {
    asm volatile("red.global.add.f32 [%0], %1;" :: "l"(p), "f"(a) : "memory");
}

// ---------- GEMM tiles ----------
__device__ __forceinline__ void load_tiles(const float* __restrict__ A, int rows, int mb,
                                           const float* __restrict__ W,
                                           float* sA, float* sB, int tid) {
    #pragma unroll
    for (int i = 0; i < 8; i++) {
        int idx = i * TPB + tid;
        int m   = idx >> 5;
        int c4  = (idx & 31) << 2;
        int row = mb + m;
        float4 val = make_float4(0.f, 0.f, 0.f, 0.f);
        if (row < rows) val = *reinterpret_cast<const float4*>(A + (long)row * 128 + c4);
        float* d = sA + m * SAS + c4;
        d[0] = val.x; d[1] = val.y; d[2] = val.z; d[3] = val.w;
    }
    #pragma unroll
    for (int i = 0; i < 16; i++) {
        int idx = i * TPB + tid;
        int k   = idx >> 5;
        int c4  = (idx & 31) << 2;
        *reinterpret_cast<float4*>(sB + k * BN + c4) =
            *reinterpret_cast<const float4*>(W + k * BN + c4);
    }
}

__device__ __forceinline__ void gemm_core(const float* sA, const float* sB,
                                          int ty, int tx, ull acc[4][4]) {
    const int m0 = ty * 4;
    const int n0 = tx * 8;
    #pragma unroll 8
    for (int k = 0; k < KK; k++) {
        float a0 = sA[(m0 + 0) * SAS + k];
        float a1 = sA[(m0 + 1) * SAS + k];
        float a2 = sA[(m0 + 2) * SAS + k];
        float a3 = sA[(m0 + 3) * SAS + k];
        // b pairs straight from smem: adjacent floats are already an f32x2
        longlong2 bA = *reinterpret_cast<const longlong2*>(sB + k * BN + n0);
        longlong2 bB = *reinterpret_cast<const longlong2*>(sB + k * BN + n0 + 4);
        ull bp0 = (ull)bA.x, bp1 = (ull)bA.y, bp2 = (ull)bB.x, bp3 = (ull)bB.y;
        ull ap;
        ap = pk(a0, a0);
        fma2(acc[0][0], ap, bp0); fma2(acc[0][1], ap, bp1);
        fma2(acc[0][2], ap, bp2); fma2(acc[0][3], ap, bp3);
        ap = pk(a1, a1);
        fma2(acc[1][0], ap, bp0); fma2(acc[1][1], ap, bp1);
        fma2(acc[1][2], ap, bp2); fma2(acc[1][3], ap, bp3);
        ap = pk(a2, a2);
        fma2(acc[2][0], ap, bp0); fma2(acc[2][1], ap, bp1);
        fma2(acc[2][2], ap, bp2); fma2(acc[2][3], ap, bp3);
        ap = pk(a3, a3);
        fma2(acc[3][0], ap, bp0); fma2(acc[3][1], ap, bp1);
        fma2(acc[3][2], ap, bp2); fma2(acc[3][3], ap, bp3);
    }
}

// ---------- kernel 0: zero ----------
__global__ void zero_kernel(int N) {
    int i = blockIdx.x * blockDim.x + threadIdx.x;
    if (i < N * 128) g_wV[i] = 0.f;
    if (i < N * 8)   g_z[i]  = 0.f;
}

// ---------- kernel 1: node QKV projections ----------
__global__ void __launch_bounds__(TPB, 2)
node_qkv_kernel(const float* __restrict__ v,
                const float* __restrict__ Wq, const float* __restrict__ bq,
                const float* __restrict__ Wk, const float* __restrict__ bk,
                const float* __restrict__ Wv, const float* __restrict__ bv,
                int N) {
    extern __shared__ float smem[];
    float* sA = smem;
    float* sB = smem + BM * SAS;
    int tid = threadIdx.x;
    int tx = tid & 15, ty = tid >> 4;

    const float* W; const float* bias; float* out;
    if      (blockIdx.y == 0) { W = Wq; bias = bq; out = g_Q; }
    else if (blockIdx.y == 1) { W = Wk; bias = bk; out = g_K; }
    else                      { W = Wv; bias = bv; out = g_V; }

    int mb = blockIdx.x * BM;
    load_tiles(v, N, mb, W, sA, sB, tid);
    __syncthreads();

    ull acc[4][4];
    #pragma unroll
    for (int i = 0; i < 4; i++)
        #pragma unroll
        for (int j = 0; j < 4; j++) acc[i][j] = 0ull;

    gemm_core(sA, sB, ty, tx, acc);

    int n0 = tx * 8;
    float bl[8];
    #pragma unroll
    for (int j = 0; j < 8; j++) bl[j] = bias[n0 + j];

    #pragma unroll
    for (int r = 0; r < 4; r++) {
        int row = mb + ty * 4 + r;
        if (row < N) {
            float o[8];
            upk(acc[r][0], o[0], o[1]); upk(acc[r][1], o[2], o[3]);
            upk(acc[r][2], o[4], o[5]); upk(acc[r][3], o[6], o[7]);
            #pragma unroll
            for (int j = 0; j < 8; j++) o[j] += bl[j];
            float4* dst = reinterpret_cast<float4*>(out + (long)row * 128 + n0);
            dst[0] = make_float4(o[0], o[1], o[2], o[3]);
            dst[1] = make_float4(o[4], o[5], o[6], o[7]);
        }
    }
}

// ---------- kernel 2: edge GEMM -> proj_e (+bias) written into eout scratch ----------
__global__ void __launch_bounds__(TPB, 2)
edge_gemm_kernel(const float* __restrict__ e,
                 const float* __restrict__ We, const float* __restrict__ be,
                 float* __restrict__ eout, int E) {
    extern __shared__ float smem[];
    float* sA = smem;
    float* sB = smem + BM * SAS;
    int tid = threadIdx.x;
    int tx = tid & 15, ty = tid >> 4;

    int mb = blockIdx.x * BM;
    load_tiles(e, E, mb, We, sA, sB, tid);
    __syncthreads();

    ull acc[4][4];
    #pragma unroll
    for (int i = 0; i < 4; i++)
        #pragma unroll
        for (int j = 0; j < 4; j++) acc[i][j] = 0ull;

    gemm_core(sA, sB, ty, tx, acc);

    int n0 = tx * 8;
    float bl[8];
    #pragma unroll
    for (int j = 0; j < 8; j++) bl[j] = be[n0 + j];

    #pragma unroll
    for (int r = 0; r < 4; r++) {
        int row = mb + ty * 4 + r;
        if (row < E) {
            float o[8];
            upk(acc[r][0], o[0], o[1]); upk(acc[r][1], o[2], o[3]);
            upk(acc[r][2], o[4], o[5]); upk(acc[r][3], o[6], o[7]);
            #pragma unroll
            for (int j = 0; j < 8; j++) o[j] += bl[j];
            float4* dst = reinterpret_cast<float4*>(eout + (long)row * 128 + n0);
            dst[0] = make_float4(o[0], o[1], o[2], o[3]);
            dst[1] = make_float4(o[4], o[5], o[6], o[7]);
        }
    }
}

// ---------- kernel 3: edge epilogue — one warp per edge, high occupancy ----------
__global__ void __launch_bounds__(256)
edge_epilogue_kernel(const float* __restrict__ envelope,
                     const int* __restrict__ src, const int* __restrict__ dst,
                     float* __restrict__ eout, int E) {
    int warp = (blockIdx.x * blockDim.x + threadIdx.x) >> 5;
    int lane = threadIdx.x & 31;
    if (warp >= E) return;

    int si = __ldg(src + warp);
    int di = __ldg(dst + warp);
    float env = __ldg(envelope + warp);

    int c = lane << 2;   // 4 floats per lane
    const float4 kv = *reinterpret_cast<const float4*>(g_K + (long)si * 128 + c);
    const float4 qv = *reinterpret_cast<const float4*>(g_Q + (long)di * 128 + c);
    const float4 vv = *reinterpret_cast<const float4*>(g_V + (long)si * 128 + c);
    float4* ep = reinterpret_cast<float4*>(eout + (long)warp * 128 + c);
    const float4 pv = *ep;

    float4 sc;
    sc.x = kv.x * qv.x * 0.25f * pv.x;
    sc.y = kv.y * qv.y * 0.25f * pv.y;
    sc.z = kv.z * qv.z * 0.25f * pv.z;
    sc.w = kv.w * qv.w * 0.25f * pv.w;

    // head = lane>>2 (16 cols per head = 4 lanes)
    float part = (sc.x + sc.y) + (sc.z + sc.w);
    part += __shfl_xor_sync(0xFFFFFFFFu, part, 1);
    part += __shfl_xor_sync(0xFFFFFFFFu, part, 2);
    float s = __expf(fminf(fmaxf(part, -5.f), 5.f));
    float es = env * s;

    *ep = sc;   // final e_out

    float* w = g_wV + (long)di * 128 + c;
    red_v4(w, vv.x * es, vv.y * es, vv.z * es, vv.w * es);
    if ((lane & 3) == 0) red_f32(g_z + (long)di * 8 + (lane >> 2), s);
}

// ---------- kernel 4: normalize ----------
__global__ void norm_kernel(float* __restrict__ vout, int N) {
    int i = blockIdx.x * blockDim.x + threadIdx.x;
    if (i < N * 128) {
        int n = i >> 7;
        int c = i & 127;
        vout[i] = g_wV[i] / (g_z[n * 8 + (c >> 4)] + 1e-6f);
    }
}

extern "C" void kernel_launch(void* const* d_in, const int* in_sizes, int n_in,
                              void* d_out, int out_size) {
    const float* v        = (const float*)d_in[0];
    const float* e        = (const float*)d_in[1];
    const float* envelope = (const float*)d_in[2];
    const float* Wq       = (const float*)d_in[3];
    const float* bq       = (const float*)d_in[4];
    const float* Wk       = (const float*)d_in[5];
    const float* bk       = (const float*)d_in[6];
    const float* Wv       = (const float*)d_in[7];
    const float* bv       = (const float*)d_in[8];
    const float* We       = (const float*)d_in[9];
    const float* be       = (const float*)d_in[10];
    const int*   src      = (const int*)d_in[11];
    const int*   dst      = (const int*)d_in[12];

    int N = in_sizes[0] / 128;
    int E = in_sizes[11];

    float* out  = (float*)d_out;
    float* vout = out;
    float* eout = out + (long)N * 128;

    size_t smem = (size_t)(BM * SAS + KK * BN) * sizeof(float);
    cudaFuncSetAttribute(node_qkv_kernel, cudaFuncAttributeMaxDynamicSharedMemorySize, (int)smem);
    cudaFuncSetAttribute(edge_gemm_kernel, cudaFuncAttributeMaxDynamicSharedMemorySize, (int)smem);

    zero_kernel<<<(N * 128 + 255) / 256, 256>>>(N);
    node_qkv_kernel<<<dim3((N + BM - 1) / BM, 3), TPB, smem>>>(v, Wq, bq, Wk, bk, Wv, bv, N);
    edge_gemm_kernel<<<(E + BM - 1) / BM, TPB, smem>>>(e, We, be, eout, E);
    edge_epilogue_kernel<<<(E * 32 + 255) / 256, 256>>>(envelope, src, dst, eout, E);
    norm_kernel<<<(N * 128 + 255) / 256, 256>>>(vout, N);
}

// round 6
// speedup vs baseline: 2.1012x; 2.1012x over previous
#include <cuda_runtime.h>
#include <cuda_bf16.h>
#include <cstdint>

static const int MAXN = 50000;

__device__ float g_Q [MAXN * 128];
__device__ float g_K [MAXN * 128];
__device__ float g_V [MAXN * 128];
__device__ float g_wV[MAXN * 128];
__device__ float g_z [MAXN * 8];

// ================= helpers =================
__device__ __forceinline__ uint32_t smem_u32(const void* p) {
    uint32_t a;
    asm("{ .reg .u64 t; cvta.to.shared.u64 t, %1; cvt.u32.u64 %0, t; }" : "=r"(a) : "l"(p));
    return a;
}
__device__ __forceinline__ void ldsm4(uint32_t& r0, uint32_t& r1, uint32_t& r2, uint32_t& r3,
                                      uint32_t addr) {
    asm volatile("ldmatrix.sync.aligned.m8n8.x4.shared.b16 {%0,%1,%2,%3}, [%4];"
                 : "=r"(r0), "=r"(r1), "=r"(r2), "=r"(r3) : "r"(addr));
}
__device__ __forceinline__ void mma16816(float* c,
                                         uint32_t a0, uint32_t a1, uint32_t a2, uint32_t a3,
                                         uint32_t b0, uint32_t b1) {
    asm volatile("mma.sync.aligned.m16n8k16.row.col.f32.bf16.bf16.f32 "
                 "{%0,%1,%2,%3}, {%4,%5,%6,%7}, {%8,%9}, {%0,%1,%2,%3};"
                 : "+f"(c[0]), "+f"(c[1]), "+f"(c[2]), "+f"(c[3])
                 : "r"(a0), "r"(a1), "r"(a2), "r"(a3), "r"(b0), "r"(b1));
}
__device__ __forceinline__ void red_v4(float* p, float a, float b, float c, float d) {
    asm volatile("red.global.add.v4.f32 [%0], {%1, %2, %3, %4};"
                 :: "l"(p), "f"(a), "f"(b), "f"(c), "f"(d) : "memory");
}
__device__ __forceinline__ void red_f32(float* p, float a) {
    asm volatile("red.global.add.f32 [%0], %1;" :: "l"(p), "f"(a) : "memory");
}

// ---- smem layout: padded 272B rows (16B pad -> ldmatrix conflict-free) ----
#define SK    272
#define S_AH  0
#define S_AL  34816
#define S_WH  69632
#define S_WL  104448
#define S_TOT 139264

#define GT 256

__device__ __forceinline__ void split_bf16(float x, __nv_bfloat16& h, __nv_bfloat16& l) {
    h = __float2bfloat16(x);
    l = __float2bfloat16(x - __bfloat162float(h));
}

// ================ HMMA GEMM: C[rows x 128] = A[rows x 128] @ W[128 x 128] + bias ================
__global__ void __launch_bounds__(GT, 1)
hmma_gemm_kernel(const float* __restrict__ A, const float* __restrict__ W,
                 const float* __restrict__ bias, float* __restrict__ C,
                 long rows, long ntiles) {
    extern __shared__ __align__(16) char smem[];
    const uint32_t sb = smem_u32(smem);
    const int tid = threadIdx.x, wid = tid >> 5, lane = tid & 31;

    // ---- convert W once: fp32 [k][n] -> split bf16 [n][k] hi/lo ----
    for (int i = tid; i < 4096; i += GT) {
        int k = i >> 5, n4 = (i & 31) << 2;
        float4 w = *reinterpret_cast<const float4*>(W + k * 128 + n4);
        const float* wp = &w.x;
        #pragma unroll
        for (int j = 0; j < 4; j++) {
            __nv_bfloat16 h, l;
            split_bf16(wp[j], h, l);
            int off = (n4 + j) * SK + k * 2;
            *reinterpret_cast<__nv_bfloat16*>(smem + S_WH + off) = h;
            *reinterpret_cast<__nv_bfloat16*>(smem + S_WL + off) = l;
        }
    }

    // ---- ldmatrix lane addresses ----
    const int q = lane >> 3, r = lane & 7;
    const uint32_t a_row = (uint32_t)(wid * 16 + r + (q & 1) * 8);
    const uint32_t a_kb  = (uint32_t)((q >> 1) * 16);
    const uint32_t aH = sb + S_AH + a_row * SK + a_kb;
    const uint32_t aL = sb + S_AL + a_row * SK + a_kb;
    const uint32_t b_off = (uint32_t)((r + (q >> 1) * 8) * SK + (q & 1) * 16);
    const uint32_t bH = sb + S_WH + b_off;
    const uint32_t bL = sb + S_WL + b_off;

    // ---- prologue: stage first A tile in registers (FULL 128-row tile = 16 float4/thread) ----
    float4 rg[16];
    long t = blockIdx.x;
    {
        #pragma unroll
        for (int i = 0; i < 16; i++) {
            int idx = i * GT + tid;
            int m = idx >> 5, c4 = (idx & 31) << 2;
            long row = t * 128 + m;
            rg[i] = (row < rows) ? *reinterpret_cast<const float4*>(A + row * 128 + c4)
                                 : make_float4(0.f, 0.f, 0.f, 0.f);
        }
    }
    __syncthreads();   // W conversion complete

    for (; t < ntiles; ) {
        // ---- store staged A tile as split bf16 (all 128 rows) ----
        #pragma unroll
        for (int i = 0; i < 16; i++) {
            int idx = i * GT + tid;
            int m = idx >> 5, c4 = (idx & 31) << 2;
            const float* ap = &rg[i].x;
            __nv_bfloat16 h0, l0, h1, l1, h2, l2, h3, l3;
            split_bf16(ap[0], h0, l0); split_bf16(ap[1], h1, l1);
            split_bf16(ap[2], h2, l2); split_bf16(ap[3], h3, l3);
            __nv_bfloat162 hp0 = __halves2bfloat162(h0, h1), hp1 = __halves2bfloat162(h2, h3);
            __nv_bfloat162 lp0 = __halves2bfloat162(l0, l1), lp1 = __halves2bfloat162(l2, l3);
            int off = m * SK + c4 * 2;
            *reinterpret_cast<uint2*>(smem + S_AH + off) =
                make_uint2(*reinterpret_cast<uint32_t*>(&hp0), *reinterpret_cast<uint32_t*>(&hp1));
            *reinterpret_cast<uint2*>(smem + S_AL + off) =
                make_uint2(*reinterpret_cast<uint32_t*>(&lp0), *reinterpret_cast<uint32_t*>(&lp1));
        }
        __syncthreads();

        // ---- prefetch next tile into registers (hides LDG under mma) ----
        long tn = t + gridDim.x;
        if (tn < ntiles) {
            #pragma unroll
            for (int i = 0; i < 16; i++) {
                int idx = i * GT + tid;
                int m = idx >> 5, c4 = (idx & 31) << 2;
                long row = tn * 128 + m;
                rg[i] = (row < rows) ? *reinterpret_cast<const float4*>(A + row * 128 + c4)
                                     : make_float4(0.f, 0.f, 0.f, 0.f);
            }
        }

        // ---- mma mainloop: 3 chains (hh, hl, lh), n-blocks in pairs for ILP ----
        float acc[64];
        #pragma unroll
        for (int i = 0; i < 64; i++) acc[i] = 0.f;

        #pragma unroll 2
        for (int ks = 0; ks < 8; ks++) {
            const uint32_t ko = ks * 32;
            uint32_t ah0, ah1, ah2, ah3, al0, al1, al2, al3;
            ldsm4(ah0, ah1, ah2, ah3, aH + ko);
            ldsm4(al0, al1, al2, al3, aL + ko);
            #pragma unroll
            for (int np = 0; np < 4; np++) {
                const uint32_t boA = (np * 2 + 0) * (16 * SK) + ko;
                const uint32_t boB = (np * 2 + 1) * (16 * SK) + ko;
                uint32_t xh0, xh1, xh2, xh3, xl0, xl1, xl2, xl3;
                uint32_t yh0, yh1, yh2, yh3, yl0, yl1, yl2, yl3;
                ldsm4(xh0, xh1, xh2, xh3, bH + boA);
                ldsm4(xl0, xl1, xl2, xl3, bL + boA);
                ldsm4(yh0, yh1, yh2, yh3, bH + boB);
                ldsm4(yl0, yl1, yl2, yl3, bL + boB);
                float* cA0 = acc + np * 16;
                float* cA1 = acc + np * 16 + 4;
                float* cB0 = acc + np * 16 + 8;
                float* cB1 = acc + np * 16 + 12;
                // hi*hi
                mma16816(cA0, ah0, ah1, ah2, ah3, xh0, xh1);
                mma16816(cA1, ah0, ah1, ah2, ah3, xh2, xh3);
                mma16816(cB0, ah0, ah1, ah2, ah3, yh0, yh1);
                mma16816(cB1, ah0, ah1, ah2, ah3, yh2, yh3);
                // hi*lo
                mma16816(cA0, ah0, ah1, ah2, ah3, xl0, xl1);
                mma16816(cA1, ah0, ah1, ah2, ah3, xl2, xl3);
                mma16816(cB0, ah0, ah1, ah2, ah3, yl0, yl1);
                mma16816(cB1, ah0, ah1, ah2, ah3, yl2, yl3);
                // lo*hi
                mma16816(cA0, al0, al1, al2, al3, xh0, xh1);
                mma16816(cA1, al0, al1, al2, al3, xh2, xh3);
                mma16816(cB0, al0, al1, al2, al3, yh0, yh1);
                mma16816(cB1, al0, al1, al2, al3, yh2, yh3);
            }
        }

        // ---- epilogue: add bias, store C ----
        {
            long gr0 = t * 128 + wid * 16 + (lane >> 2);
            long gr1 = gr0 + 8;
            #pragma unroll
            for (int i8 = 0; i8 < 16; i8++) {
                int col = i8 * 8 + (lane & 3) * 2;
                float2 bb = *reinterpret_cast<const float2*>(bias + col);
                const float* cp = acc + i8 * 4;
                if (gr0 < rows) {
                    float2 o = make_float2(cp[0] + bb.x, cp[1] + bb.y);
                    *reinterpret_cast<float2*>(C + gr0 * 128 + col) = o;
                }
                if (gr1 < rows) {
                    float2 o = make_float2(cp[2] + bb.x, cp[3] + bb.y);
                    *reinterpret_cast<float2*>(C + gr1 * 128 + col) = o;
                }
            }
        }
        __syncthreads();   // all warps done reading smem before next STS
        t = tn;
    }
}

// ================= non-GEMM kernels (unchanged) =================
__global__ void zero_kernel(int N) {
    int i = blockIdx.x * blockDim.x + threadIdx.x;
    if (i < N * 128) g_wV[i] = 0.f;
    if (i < N * 8)   g_z[i]  = 0.f;
}

__global__ void __launch_bounds__(256)
edge_epilogue_kernel(const float* __restrict__ envelope,
                     const int* __restrict__ src, const int* __restrict__ dst,
                     float* __restrict__ eout, int E) {
    int warp = (blockIdx.x * blockDim.x + threadIdx.x) >> 5;
    int lane = threadIdx.x & 31;
    if (warp >= E) return;

    int si = __ldg(src + warp);
    int di = __ldg(dst + warp);
    float env = __ldg(envelope + warp);

    int c = lane << 2;
    const float4 kv = *reinterpret_cast<const float4*>(g_K + (long)si * 128 + c);
    const float4 qv = *reinterpret_cast<const float4*>(g_Q + (long)di * 128 + c);
    const float4 vv = *reinterpret_cast<const float4*>(g_V + (long)si * 128 + c);
    float4* ep = reinterpret_cast<float4*>(eout + (long)warp * 128 + c);
    const float4 pv = *ep;

    float4 sc;
    sc.x = kv.x * qv.x * 0.25f * pv.x;
    sc.y = kv.y * qv.y * 0.25f * pv.y;
    sc.z = kv.z * qv.z * 0.25f * pv.z;
    sc.w = kv.w * qv.w * 0.25f * pv.w;

    float part = (sc.x + sc.y) + (sc.z + sc.w);
    part += __shfl_xor_sync(0xFFFFFFFFu, part, 1);
    part += __shfl_xor_sync(0xFFFFFFFFu, part, 2);
    float s = __expf(fminf(fmaxf(part, -5.f), 5.f));
    float es = env * s;

    *ep = sc;

    float* w = g_wV + (long)di * 128 + c;
    red_v4(w, vv.x * es, vv.y * es, vv.z * es, vv.w * es);
    if ((lane & 3) == 0) red_f32(g_z + (long)di * 8 + (lane >> 2), s);
}

__global__ void norm_kernel(float* __restrict__ vout, int N) {
    int i = blockIdx.x * blockDim.x + threadIdx.x;
    if (i < N * 128) {
        int n = i >> 7;
        int c = i & 127;
        vout[i] = g_wV[i] / (g_z[n * 8 + (c >> 4)] + 1e-6f);
    }
}

extern "C" void kernel_launch(void* const* d_in, const int* in_sizes, int n_in,
                              void* d_out, int out_size) {
    const float* v        = (const float*)d_in[0];
    const float* e        = (const float*)d_in[1];
    const float* envelope = (const float*)d_in[2];
    const float* Wq       = (const float*)d_in[3];
    const float* bq       = (const float*)d_in[4];
    const float* Wk       = (const float*)d_in[5];
    const float* bk       = (const float*)d_in[6];
    const float* Wv       = (const float*)d_in[7];
    const float* bv       = (const float*)d_in[8];
    const float* We       = (const float*)d_in[9];
    const float* be       = (const float*)d_in[10];
    const int*   src      = (const int*)d_in[11];
    const int*   dst      = (const int*)d_in[12];

    int N = in_sizes[0] / 128;
    int E = in_sizes[11];

    float* out  = (float*)d_out;
    float* vout = out;
    float* eout = out + (long)N * 128;

    float *gq, *gk, *gv;
    cudaGetSymbolAddress((void**)&gq, g_Q);
    cudaGetSymbolAddress((void**)&gk, g_K);
    cudaGetSymbolAddress((void**)&gv, g_V);
    cudaFuncSetAttribute(hmma_gemm_kernel, cudaFuncAttributeMaxDynamicSharedMemorySize, S_TOT);

    long tilesN = (N + 127) / 128;
    long tilesE = (E + 127) / 128;
    int gridN = (int)((tilesN < 148) ? tilesN : 148);
    int gridE = (int)((tilesE < 148) ? tilesE : 148);

    zero_kernel<<<(N * 128 + 255) / 256, 256>>>(N);
    hmma_gemm_kernel<<<gridN, GT, S_TOT>>>(v, Wq, bq, gq, N, tilesN);
    hmma_gemm_kernel<<<gridN, GT, S_TOT>>>(v, Wk, bk, gk, N, tilesN);
    hmma_gemm_kernel<<<gridN, GT, S_TOT>>>(v, Wv, bv, gv, N, tilesN);
    hmma_gemm_kernel<<<gridE, GT, S_TOT>>>(e, We, be, eout, E, tilesE);
    edge_epilogue_kernel<<<(E * 32 + 255) / 256, 256>>>(envelope, src, dst, eout, E);
    norm_kernel<<<(N * 128 + 255) / 256, 256>>>(vout, N);
}